// round 11
// baseline (speedup 1.0000x reference)
#include <cuda_runtime.h>
#include <cuda_bf16.h>
#include <cstdint>

// out = relu( [residues | atoms | meanS(atoms) | meanD(atoms)] @ [Wr; Wv; Wsr; Wdr] )
// mma.sync m16n8k16 bf16, 3-way split (hi*hi + hi*lo + lo*hi), fp32 reg accum.
// R11 = R10 resubmitted verbatim (R10 bench was a container-level infra failure;
// the kernel itself never ran). Change under test: MMA issue order restructured
// into 3 passes so consecutive MMAs never share an accumulator (R9 issued the 3
// split-MMAs back-to-back into the SAME acc register -> serial RAW chain ->
// tensor pipe capped at ~1/3, exactly the 34% ncu measured).

namespace {
constexpr int NA = 100000, AD = 12, RD = 1024, FD = 128, KN = 10;
constexpr int MT = 128;             // rows per CTA
constexpr int KC = 64;              // K chunk
constexpr int NCH = RD / KC;        // 16 residue chunks
constexpr int NCHT = NCH + 1;       // +1 ext chunk (atoms|meanS|meanD)
constexpr int CTAS = (NA + MT - 1) / MT;  // 782
constexpr long long NF = (long long)NA * FD;
constexpr long long NK = (long long)NA * KN;

// smem layout (bytes)
constexpr int SM_AHI = 0;                  // 16 KB A hi tile (bf16, 128B rows, sw128)
constexpr int SM_ALO = 16384;              // 16 KB A lo tile
constexpr int SM_STG = 32768;              // 32 KB f32 stage (two 16KB halves, 128B rows)
constexpr int SM_B   = 65536;              // 32 KB B fragments (2048 x uint4, linear)
constexpr int SM_TOTAL = 98304;            // 96 KB -> 2 CTAs/SM

constexpr int NFRAGS = NCHT * 16 * 4 * 32; // [chunk][nfrag16][t4][lane32]
}  // namespace

__device__ uint4 g_Bfrag[NFRAGS];  // B in mma-frag order: (hi0,hi1,lo0,lo1)

static __device__ __forceinline__ uint32_t sw128(uint32_t off) { return off ^ ((off >> 3) & 0x70); }
static __device__ __forceinline__ uint32_t smem_u32(const void* p) {
  uint32_t a;
  asm("{ .reg .u64 t; cvta.to.shared.u64 t, %1; cvt.u32.u64 %0, t; }" : "=r"(a) : "l"(p));
  return a;
}
static __device__ __forceinline__ void ldm4(uint32_t r[4], uint32_t addr) {
  asm volatile("ldmatrix.sync.aligned.m8n8.x4.shared.b16 {%0,%1,%2,%3}, [%4];"
               : "=r"(r[0]), "=r"(r[1]), "=r"(r[2]), "=r"(r[3]) : "r"(addr));
}
static __device__ __forceinline__ void mma16816(float c[4], const uint32_t a[4],
                                                uint32_t b0, uint32_t b1) {
  asm volatile(
      "mma.sync.aligned.m16n8k16.row.col.f32.bf16.bf16.f32 "
      "{%0,%1,%2,%3}, {%4,%5,%6,%7}, {%8,%9}, {%0,%1,%2,%3};"
      : "+f"(c[0]), "+f"(c[1]), "+f"(c[2]), "+f"(c[3])
      : "r"(a[0]), "r"(a[1]), "r"(a[2]), "r"(a[3]), "r"(b0), "r"(b1));
}
static __device__ __forceinline__ uint16_t bfbits(__nv_bfloat16 h) {
  return *reinterpret_cast<uint16_t*>(&h);
}
static __device__ __forceinline__ void cpasync16(uint32_t dst, const void* src, int srcsz) {
  asm volatile("cp.async.cg.shared.global [%0], [%1], 16, %2;"
               :: "r"(dst), "l"(src), "r"(srcsz) : "memory");
}
// pair = {lo: a, hi: b} as bf16x2
static __device__ __forceinline__ uint32_t bf16x2_rn(float a, float b) {
  uint32_t r;
  asm("cvt.rn.bf16x2.f32 %0, %1, %2;" : "=r"(r) : "f"(b), "f"(a));
  return r;
}
#define CP_COMMIT()  asm volatile("cp.async.commit_group;" ::: "memory")
#define CP_WAIT(n)   asm volatile("cp.async.wait_group %0;" :: "n"(n) : "memory")

// ---- prep: B-fragment bake + index passthrough, merged into ONE launch ----
__global__ void prep_kernel(const float* __restrict__ Wr, const float* __restrict__ Wv,
                            const float* __restrict__ Wsr, const float* __restrict__ Wdr,
                            const int* __restrict__ s0, const int* __restrict__ d0,
                            const int* __restrict__ s1, const int* __restrict__ d1,
                            float* __restrict__ out) {
  long long i = (long long)blockIdx.x * blockDim.x + threadIdx.x;
  if (i < NFRAGS) {
    int ii = (int)i;
    int lane = ii & 31, t = (ii >> 5) & 3, fn = (ii >> 7) & 15, c = ii >> 11;
    int n = fn * 8 + (lane >> 2);
    int k0 = t * 16 + 2 * (lane & 3);
    uint16_t h[4], l[4];
#pragma unroll
    for (int e = 0; e < 4; e++) {
      int kk = k0 + (e & 1) + (e >> 1) * 8;  // {k0,k0+1,k0+8,k0+9}
      float val = 0.f;
      if (c < NCH)          val = Wr[(c * KC + kk) * FD + n];
      else if (kk < AD)     val = Wv[kk * FD + n];
      else if (kk < 2 * AD) val = Wsr[(kk - AD) * FD + n];
      else if (kk < 3 * AD) val = Wdr[(kk - 2 * AD) * FD + n];
      __nv_bfloat16 hb = __float2bfloat16_rn(val);
      __nv_bfloat16 lb = __float2bfloat16_rn(val - __bfloat162float(hb));
      h[e] = bfbits(hb); l[e] = bfbits(lb);
    }
    uint4 o;
    o.x = (uint32_t)h[0] | ((uint32_t)h[1] << 16);
    o.y = (uint32_t)h[2] | ((uint32_t)h[3] << 16);
    o.z = (uint32_t)l[0] | ((uint32_t)l[1] << 16);
    o.w = (uint32_t)l[2] | ((uint32_t)l[3] << 16);
    g_Bfrag[ii] = o;
  }
  if (i < 4 * NK) {
    int reg = (int)(i / NK);
    long long j = i % NK;
    const int* src = reg == 0 ? s0 : reg == 1 ? d0 : reg == 2 ? s1 : d1;
    long long base = reg == 0 ? NF : reg == 1 ? NF + NK
                   : reg == 2 ? 2 * NF + 2 * NK : 2 * NF + 3 * NK;
    out[base + j] = (float)src[j];
  }
}

// ---- main fused kernel ----
__global__ void __launch_bounds__(256, 2)
gnn_mma_kernel(const float* __restrict__ atoms0, const float* __restrict__ resd0,
               const int* __restrict__ same0, const int* __restrict__ diff0,
               const float* __restrict__ atoms1, const float* __restrict__ resd1,
               const int* __restrict__ same1, const int* __restrict__ diff1,
               float* __restrict__ out) {
  extern __shared__ char smem[];
  const int tid = threadIdx.x, wid = tid >> 5, lane = tid & 31;
  const int p = blockIdx.x / CTAS, tile = blockIdx.x % CTAS;
  const float* atoms = p ? atoms1 : atoms0;
  const float* resd  = p ? resd1  : resd0;
  const int*   same  = p ? same1  : same0;
  const int*   diff  = p ? diff1  : diff0;
  float* outp = out + (p ? (NF + 2 * NK) : 0);
  const int r0 = tile * MT;
  const uint32_t sbase = smem_u32(smem);
  const uint32_t hiB = sbase + SM_AHI, loB = sbase + SM_ALO;
  const uint32_t stgB = sbase + SM_STG, bB = sbase + SM_B;

  // f32 residues chunk c -> stage (two 16KB halves, 128B rows, sw128)
  auto stageChunk = [&](int c) {
#pragma unroll
    for (int j = 0; j < 8; j++) {
      int u = tid + 256 * j;            // 16B unit: r = u>>4, kq = u&15
      int r = u >> 4, kq = u & 15;
      long long g = r0 + r;
      const float* src = resd + (g < NA ? g * RD + (long long)c * KC + kq * 4 : 0);
      uint32_t dst = stgB + (uint32_t)(kq >> 3) * 16384 +
                     sw128((uint32_t)r * 128 + (uint32_t)(kq & 7) * 16);
      cpasync16(dst, src, g < NA ? 16 : 0);
    }
  };
  // B fragments chunk cb -> smem (straight 32 KB copy, linear)
  auto bstage = [&](int cb) {
    const uint4* src = g_Bfrag + cb * 2048;
#pragma unroll
    for (int j = 0; j < 8; j++) {
      int u = tid + 256 * j;
      cpasync16(bB + (uint32_t)u * 16, src + u, 16);
    }
  };

  // prologue: B(ext) first in FIFO, then stage(0)
  bstage(NCH);   CP_COMMIT();   // G: B(ext)
  stageChunk(0); CP_COMMIT();   // G: stage(0)

  // zero A hi/lo tiles (ext pad cols + tail rows)
  {
    uint4 z = make_uint4(0, 0, 0, 0);
    uint4* e = (uint4*)(smem + SM_AHI);
#pragma unroll
    for (int j = 0; j < 8; j++) e[tid + 256 * j] = z;  // 32 KB
  }
  __syncthreads();

  // ---- prepass: ext rows = [atoms | meanSame | meanDiff | 0] into A tiles ----
  for (int rr = 0; rr < 16; rr++) {
    int i = wid * 16 + rr;
    long long g = r0 + i;
    float av = 0.f;
    int idxreg = -1;
    if (g < NA) {
      if (lane < AD) av = atoms[g * AD + lane];
      if (lane < KN)          idxreg = same[g * KN + lane];
      else if (lane < 2 * KN) idxreg = diff[g * KN + (lane - KN)];
    }
    float ssum = 0.f, dsum = 0.f;
    int scnt = 0, dcnt = 0;
#pragma unroll
    for (int k = 0; k < KN; k++) {
      int si = __shfl_sync(0xffffffffu, idxreg, k);
      int di = __shfl_sync(0xffffffffu, idxreg, KN + k);
      if (si > -1) { scnt++; if (lane < AD) ssum += atoms[(long long)si * AD + lane]; }
      if (di > -1) { dcnt++; if (lane < AD) dsum += atoms[(long long)di * AD + lane]; }
    }
    if (lane < AD && g < NA) {
      float vals[3] = {av, ssum * (1.f / (float)(scnt > 1 ? scnt : 1)),
                           dsum * (1.f / (float)(dcnt > 1 ? dcnt : 1))};
#pragma unroll
      for (int q = 0; q < 3; q++) {
        __nv_bfloat16 hb = __float2bfloat16_rn(vals[q]);
        __nv_bfloat16 lb = __float2bfloat16_rn(vals[q] - __bfloat162float(hb));
        uint32_t off = sw128((uint32_t)i * 128 + (uint32_t)(q * AD + lane) * 2);
        *(__nv_bfloat16*)(smem + SM_AHI + off) = hb;
        *(__nv_bfloat16*)(smem + SM_ALO + off) = lb;
      }
    }
  }

  // warp tile: 2x4 grid, each warp 64(M) x 32(N)
  const int wm = (wid >> 2) * 64;
  const int fnBase = (wid & 3) * 4;
  float acc[4][4][4];
#pragma unroll
  for (int a = 0; a < 4; a++)
#pragma unroll
    for (int b = 0; b < 4; b++)
#pragma unroll
      for (int e = 0; e < 4; e++) acc[a][b][e] = 0.f;

  // compute one chunk. 3 passes per t-step; within a pass all 16 MMAs hit
  // DISTINCT accumulators (fully pipelined); acc reuse distance across passes
  // is 12-16 MMAs >> HMMA latency. A fragments ldmatrix'd one mf ahead so the
  // previous mf's 4 MMAs hide the LDS latency.
  auto computeChunk = [&]() {
#pragma unroll
    for (int t = 0; t < 4; t++) {
      uint4 bq[4];
#pragma unroll
      for (int nf = 0; nf < 4; nf++) {
        uint32_t ba = bB + (uint32_t)((((fnBase + nf) * 4 + t) << 5) + lane) * 16;
        asm volatile("ld.shared.v4.u32 {%0,%1,%2,%3}, [%4];"
                     : "=r"(bq[nf].x), "=r"(bq[nf].y), "=r"(bq[nf].z), "=r"(bq[nf].w)
                     : "r"(ba));
      }
      uint32_t colsw = sw128(((uint32_t)(lane & 15)) * 128 +
                             (uint32_t)(t * 2 + (lane >> 4)) * 16);
      uint32_t aoff = (uint32_t)wm * 128 + colsw;   // + mf*2048

#pragma unroll
      for (int pass = 0; pass < 3; pass++) {
        const uint32_t srcB = (pass < 2) ? hiB : loB;
        uint32_t a0[4], a1[4];
        ldm4(a0, srcB + aoff);
#pragma unroll
        for (int mf = 0; mf < 4; mf++) {
          if (mf < 3) ldm4(a1, srcB + aoff + (uint32_t)(mf + 1) * 2048);
#pragma unroll
          for (int nf = 0; nf < 4; nf++) {
            if (pass == 1) mma16816(acc[mf][nf], a0, bq[nf].z, bq[nf].w);  // hi*lo
            else           mma16816(acc[mf][nf], a0, bq[nf].x, bq[nf].y);  // hi*hi / lo*hi
          }
          if (mf < 3) {
            a0[0] = a1[0]; a0[1] = a1[1]; a0[2] = a1[2]; a0[3] = a1[3];
          }
        }
      }
    }
  };

  // ---- ext chunk first: wait B(ext), BARRIER, then compute ----
  CP_WAIT(1);       // own B(ext) copies done [stage(0) pending]
  __syncthreads();  // ALL threads' B(ext) copies done (prepass also barriered here)
  computeChunk();

  // ---- residue chunks: single-buffered stage/B/A-tile ----
  for (int c = 0; c < NCH; c++) {
    __syncthreads();            // all warps done with previous compute (B, A free)
    bstage(c); CP_COMMIT();     // G: B(c)
    CP_WAIT(1);                 // own stage(c) copies done [B(c) pending]
    __syncthreads();            // ALL threads' stage(c) copies visible
    // convert stage -> bf16 hi/lo A tiles
#pragma unroll
    for (int j = 0; j < 4; j++) {
      int u = tid + 256 * j;
      int r = u >> 3, k0 = (u & 7) * 8;
      uint32_t half = (uint32_t)(k0 >> 5) * 16384;
      uint32_t x = (uint32_t)r * 128 + (uint32_t)(k0 & 31) * 4;
      float4 f0, f1;
      asm volatile("ld.shared.v4.f32 {%0,%1,%2,%3}, [%4];"
                   : "=f"(f0.x), "=f"(f0.y), "=f"(f0.z), "=f"(f0.w)
                   : "r"(stgB + half + sw128(x)));
      asm volatile("ld.shared.v4.f32 {%0,%1,%2,%3}, [%4];"
                   : "=f"(f1.x), "=f"(f1.y), "=f"(f1.z), "=f"(f1.w)
                   : "r"(stgB + half + sw128(x + 16)));
      float v[8] = {f0.x, f0.y, f0.z, f0.w, f1.x, f1.y, f1.z, f1.w};
      uint32_t hp[4], lp[4];
#pragma unroll
      for (int q = 0; q < 4; q++) {
        uint32_t hpair = bf16x2_rn(v[2 * q], v[2 * q + 1]);
        float h0 = __uint_as_float(hpair << 16);
        float h1 = __uint_as_float(hpair & 0xFFFF0000u);
        hp[q] = hpair;
        lp[q] = bf16x2_rn(v[2 * q] - h0, v[2 * q + 1] - h1);
      }
      uint32_t ao = sw128((uint32_t)r * 128 + (uint32_t)k0 * 2);
      *(uint4*)(smem + SM_AHI + ao) = *(const uint4*)hp;
      *(uint4*)(smem + SM_ALO + ao) = *(const uint4*)lp;
    }
    __syncthreads();            // A tiles ready; stage buffer free
    if (c + 1 < NCH) stageChunk(c + 1);
    CP_COMMIT();                // G: stage(c+1) (empty group at tail keeps FIFO uniform)
    CP_WAIT(1);                 // own B(c) copies done [stage(c+1) pending]
    __syncthreads();            // ALL threads' B(c) copies visible
    computeChunk();
  }

  // ---- epilogue: relu + float2 stores straight from fragments ----
  const int wn = (wid & 3) * 32;
#pragma unroll
  for (int mf = 0; mf < 4; mf++) {
    long long r = (long long)r0 + wm + mf * 16 + (lane >> 2);
#pragma unroll
    for (int nf = 0; nf < 4; nf++) {
      int cb = wn + nf * 8 + 2 * (lane & 3);
      if (r < NA) {
        float2 w;
        w.x = fmaxf(acc[mf][nf][0], 0.f);
        w.y = fmaxf(acc[mf][nf][1], 0.f);
        *(float2*)(outp + r * FD + cb) = w;
      }
      if (r + 8 < NA) {
        float2 w;
        w.x = fmaxf(acc[mf][nf][2], 0.f);
        w.y = fmaxf(acc[mf][nf][3], 0.f);
        *(float2*)(outp + (r + 8) * FD + cb) = w;
      }
    }
  }
}

extern "C" void kernel_launch(void* const* d_in, const int* in_sizes, int n_in,
                              void* d_out, int out_size) {
  const float* atoms0 = (const float*)d_in[0];
  const float* resd0  = (const float*)d_in[1];
  const int*   same0  = (const int*)d_in[2];
  const int*   diff0  = (const int*)d_in[3];
  const float* atoms1 = (const float*)d_in[4];
  const float* resd1  = (const float*)d_in[5];
  const int*   same1  = (const int*)d_in[6];
  const int*   diff1  = (const int*)d_in[7];
  const float* Wv  = (const float*)d_in[8];
  const float* Wr  = (const float*)d_in[9];
  const float* Wsr = (const float*)d_in[10];
  const float* Wdr = (const float*)d_in[11];
  float* out = (float*)d_out;

  cudaFuncSetAttribute(gnn_mma_kernel, cudaFuncAttributeMaxDynamicSharedMemorySize, SM_TOTAL);

  long long pn = 4 * NK;  // covers NFRAGS too
  prep_kernel<<<(int)((pn + 255) / 256), 256>>>(Wr, Wv, Wsr, Wdr,
                                                same0, diff0, same1, diff1, out);
  gnn_mma_kernel<<<2 * CTAS, 256, SM_TOTAL>>>(atoms0, resd0, same0, diff0,
                                              atoms1, resd1, same1, diff1, out);
}